// round 8
// baseline (speedup 1.0000x reference)
#include <cuda_runtime.h>
#include <cuda_fp16.h>
#include <mma.h>
#include <cstdint>
#include <cstddef>

using namespace nvcuda;

#define Tt 10
#define Bb 16
#define Ss 200
#define Dd 768
#define K5 3840            // 5*D
#define NPAD 2432          // 1216 (fwd block) + 1216 (bwd block)
#define NDIRBASE 1216
#define Mm 32000           // T*S*B
#define LDK 320            // padded recurrent K in GLOBAL h buffer (halves)
#define LDW 344            // Whh shared stride (halves)
#define LDA 20             // accS stride (floats)
#define NCTA_L 25          // LSTM CTAs: each owns 12 h-cols per direction
#define CPD 12

// ---------------- device scratch (allocation-free) ----------------
__device__ __half g_X[(size_t)Mm * K5];      // 245.8 MB fp16
__device__ __half g_W[(size_t)NPAD * K5];    // 18.7 MB fp16
__device__ float g_C[(size_t)Mm * NPAD];     // 311.3 MB
__device__ float g_ws[Tt * Bb * Ss];
__device__ float g_we[Tt * Bb * Ss];
__device__ float g_wbs[Bb * Ss];
__device__ float g_wbe[Bb * Ss];
__device__ float g_y[(size_t)Tt * Ss * Bb * 600];  // [t][s][b][2H]
__device__ __half g_h[2 * 2 * Bb * LDK];     // [dir][parity][b][LDK] fp16
__device__ unsigned g_slots[NCTA_L * 8];     // per-CTA barrier slots, 32B stride

// ---------------- helpers ----------------
__device__ __forceinline__ uint32_t smem_u32(const void* p) {
    uint32_t a;
    asm("{ .reg .u64 t; cvta.to.shared.u64 t, %1; cvt.u32.u64 %0, t; }" : "=r"(a) : "l"(p));
    return a;
}
__device__ __forceinline__ void cp16(uint32_t d, const void* s) {
    asm volatile("cp.async.cg.shared.global [%0], [%1], 16;" :: "r"(d), "l"(s) : "memory");
}

// ---------------- kernel 0: init (also shifts ncu capture onto k_lstm) -------
__global__ void k_init() {
    int i = threadIdx.x + blockIdx.x * blockDim.x;
    if (i < NCTA_L * 8) g_slots[i] = 0u;
    for (int e = i; e < 2 * 2 * Bb * LDK; e += gridDim.x * blockDim.x)
        g_h[e] = __float2half(0.f);
}

// ---------------- kernel 1: fused attention weights ----------------
__global__ void k_weights(const float* __restrict__ sp, const float* __restrict__ ep,
                          const float* __restrict__ cp,
                          const float* __restrict__ bsp, const float* __restrict__ bep,
                          const float* __restrict__ bcp,
                          const float* __restrict__ um, const float* __restrict__ nm,
                          const float* __restrict__ am) {
    int idx = blockIdx.x * blockDim.x + threadIdx.x;
    if (idx >= Tt * Bb * Ss) return;
    int t = idx / (Bb * Ss);
    int r = idx % (Bb * Ss);
    int b = r / Ss;
    int s = r % Ss;
    // masks are [B,T,S]
    float amv = am[(b * Tt + t) * Ss + s];
    float umv = um[(b * Tt + t) * Ss + s];
    float nmv = nm[(b * Tt + t) * Ss + s];
    const float* c = cp + (t * Bb + b) * 4;
    float wb = amv * c[0] + umv * c[1] + nmv * c[2];
    g_ws[idx] = sp[idx] * wb;
    g_we[idx] = ep[idx] * wb;
    if (t == 0) {
        const float* bc = bcp + b * 4;
        float wbb = amv * bc[0] + umv * bc[1] + nmv * bc[2];
        g_wbs[b * Ss + s] = bsp[b * Ss + s] * wbb;
        g_wbe[b * Ss + s] = bep[b * Ss + s] * wbb;
    }
}

// ---------------- kernel 2: stacked + gate-permuted fp16 Wih -----------------
__global__ void k_wpad(const float* __restrict__ wf, const float* __restrict__ wb) {
    int rrow = blockIdx.x;
    int dir = rrow >= NDIRBASE;
    int rp = dir ? rrow - NDIRBASE : rrow;
    const float* src = nullptr;
    if (rp < 1200) {
        int tile = rp >> 4, gate = (rp >> 2) & 3, cc = rp & 3;
        int srow = gate * 300 + tile * 4 + cc;
        src = (dir ? wb : wf) + (size_t)srow * K5;
    }
    __half* dst = g_W + (size_t)rrow * K5;
    for (int c = threadIdx.x * 4; c < K5; c += blockDim.x * 4) {
        float4 v = make_float4(0.f, 0.f, 0.f, 0.f);
        if (src) v = *(const float4*)(src + c);
        __half2 a = __floats2half2_rn(v.x, v.y);
        __half2 b2 = __floats2half2_rn(v.z, v.w);
        *(__half2*)(dst + c) = a;
        *(__half2*)(dst + c + 2) = b2;
    }
}

// ---------------- kernel 3: build X (fp16) ----------------
__global__ void k_xbuild(const float* __restrict__ seq) {
    int m = blockIdx.x;          // ((t*200+s)*16+b)
    int b = m & 15;
    int ts = m >> 4;
    int s = ts % Ss;
    int t = ts / Ss;
    int tp = (t > 0) ? (t - 1) : 0;
    int c = threadIdx.x * 4;     // 192 threads -> 768 cols
    const float4 sv = *(const float4*)(seq + (((size_t)(t * Bb + b) * Ss + s) * Dd) + c);
    const float4 pv = *(const float4*)(seq + (((size_t)(tp * Bb + b) * Ss + s) * Dd) + c);
    int widx = (t * Bb + b) * Ss + s;
    float w1 = g_ws[widx], w2 = g_we[widx];
    float wp1, wp2;
    if (t > 0) {
        int pidx = ((t - 1) * Bb + b) * Ss + s;
        wp1 = g_ws[pidx];
        wp2 = g_we[pidx];
    } else {
        wp1 = g_wbs[b * Ss + s];
        wp2 = g_wbe[b * Ss + s];
    }
    __half* X = g_X + (size_t)m * K5 + c;
#define R4(off, a, wgt) do { \
        __half2 _h0 = __floats2half2_rn((a).x * (wgt), (a).y * (wgt)); \
        __half2 _h1 = __floats2half2_rn((a).z * (wgt), (a).w * (wgt)); \
        *(__half2*)(X + (off)) = _h0; \
        *(__half2*)(X + (off) + 2) = _h1; } while (0)
    R4(0,    sv, 1.f);
    R4(768,  sv, w1);
    R4(1536, sv, w2);
    R4(2304, pv, wp1);
    R4(3072, pv, wp2);
#undef R4
}

// ---------------- kernel 4: pipelined fp16 wmma GEMM  C = X * W^T ------------
#define GP2 40
#define STAGEH (2 * 128 * GP2)         // halves per stage (A + B)
#define GSMEM (3 * STAGEH * 2)         // 61440 B -> 2 CTAs/SM
#define NK (K5 / 32)                   // 120 k-tiles

__global__ void __launch_bounds__(256) k_gemm2() {
    extern __shared__ __half smh[];
    int tid = threadIdx.x;
    int mt = blockIdx.y, nt = blockIdx.x;
    uint32_t sbase = smem_u32(smh);

    int wid = tid >> 5;
    int wy = wid >> 1, wx = wid & 1;   // 4x2 warps; warp tile 32x64

    int lrow0 = tid >> 2;              // 64 rows per pass, 2 passes
    int lc4 = tid & 3;                 // 4 chunks of 8 halves per row

    const __half* AG = g_X + (size_t)(mt * 128) * K5;
    const __half* BG = g_W + (size_t)(nt * 128) * K5;

    wmma::fragment<wmma::accumulator, 16, 16, 16, float> acc[2][4];
#pragma unroll
    for (int i = 0; i < 2; ++i)
#pragma unroll
        for (int j = 0; j < 4; ++j) wmma::fill_fragment(acc[i][j], 0.f);

#define LOADSTAGE(kt, st) do { \
        uint32_t sa = sbase + (st) * STAGEH * 2; \
        uint32_t sbb = sa + 128 * GP2 * 2; \
        int kof = (kt) * 32 + lc4 * 8; \
        _Pragma("unroll") \
        for (int i = 0; i < 2; ++i) { \
            int row = lrow0 + i * 64; \
            cp16(sa  + (row * GP2 + lc4 * 8) * 2, AG + (size_t)row * K5 + kof); \
            cp16(sbb + (row * GP2 + lc4 * 8) * 2, BG + (size_t)row * K5 + kof); \
        } \
        asm volatile("cp.async.commit_group;" ::: "memory"); \
    } while (0)

    LOADSTAGE(0, 0);
    LOADSTAGE(1, 1);

    for (int kt = 0; kt < NK; ++kt) {
        int st = kt % 3;
        asm volatile("cp.async.wait_group 1;" ::: "memory");
        __syncthreads();
        if (kt + 2 < NK) {
            LOADSTAGE(kt + 2, (kt + 2) % 3);
        } else {
            asm volatile("cp.async.commit_group;" ::: "memory");
        }
        const __half* As = smh + st * STAGEH;
        const __half* Bs = As + 128 * GP2;
#pragma unroll
        for (int ks = 0; ks < 2; ++ks) {
            wmma::fragment<wmma::matrix_a, 16, 16, 16, half, wmma::row_major> a0, a1;
            wmma::load_matrix_sync(a0, As + (wy * 32) * GP2 + ks * 16, GP2);
            wmma::load_matrix_sync(a1, As + (wy * 32 + 16) * GP2 + ks * 16, GP2);
#pragma unroll
            for (int j = 0; j < 4; ++j) {
                wmma::fragment<wmma::matrix_b, 16, 16, 16, half, wmma::col_major> bf;
                wmma::load_matrix_sync(bf, Bs + (wx * 64 + j * 16) * GP2 + ks * 16, GP2);
                wmma::mma_sync(acc[0][j], a0, bf, acc[0][j]);
                wmma::mma_sync(acc[1][j], a1, bf, acc[1][j]);
            }
        }
    }
#undef LOADSTAGE

#pragma unroll
    for (int i = 0; i < 2; ++i)
#pragma unroll
        for (int j = 0; j < 4; ++j) {
            float* cp = g_C + (size_t)(mt * 128 + wy * 32 + i * 16) * NPAD
                        + nt * 128 + wx * 64 + j * 16;
            wmma::store_matrix_sync(cp, acc[i][j], NPAD, wmma::mem_row_major);
        }
}

// ---------------- kernel 5: persistent bidirectional LSTM scan ----------------
// 25 CTAs x 384 threads. CTA owns 12 h-cols per direction (3 gate-tiles).
// 12 warps: (dir 2) x (tile 3) x (k-half 2); Whh B-frags register-resident;
// A-frags straight from L2; per-thread c state; warp-ballot flag polling.
__device__ __forceinline__ float sigm(float x) {
    return 1.f / (1.f + __expf(-x));
}
__device__ __forceinline__ float tanh_fast(float x) {
    x = fminf(fmaxf(x, -15.f), 15.f);
    float e = __expf(-2.f * x);
    return (1.f - e) / (1.f + e);
}

extern __shared__ char smraw[];
__global__ void __launch_bounds__(384, 1) k_lstm(
        const float* __restrict__ whf, const float* __restrict__ whb,
        const float* __restrict__ bihf, const float* __restrict__ bhhf,
        const float* __restrict__ bihb, const float* __restrict__ bhhb) {
    __half* WhhS = (__half*)smraw;                          // [2][3][16][LDW]
    float* accS  = (float*)(smraw + 2 * 3 * 16 * LDW * 2);  // [12][16][LDA]
    float* bS    = accS + 12 * 16 * LDA;                    // [96]

    int tid = threadIdx.x;
    int cta = blockIdx.x;

    // prologue: gate-permuted Whh slices into shared (fp16)
    for (int e = tid; e < 2 * 3 * 16 * LDW; e += 384) {
        int k = e % LDW;
        int rr = (e / LDW) % 16;
        int tau = (e / (16 * LDW)) % 3;
        int d = e / (3 * 16 * LDW);
        int gate = rr >> 2, cc = rr & 3;
        int srow = gate * 300 + cta * CPD + tau * 4 + cc;
        float v = 0.f;
        if (k < 300) v = (d ? whb : whf)[srow * 300 + k];
        WhhS[e] = __float2half(v);
    }
    if (tid < 96) {
        int d = tid / 48, r = tid % 48;
        int tau = r >> 4, rr = r & 15;
        int gate = rr >> 2, cc = rr & 3;
        int srow = gate * 300 + cta * CPD + tau * 4 + cc;
        bS[tid] = d ? (bihb[srow] + bhhb[srow]) : (bihf[srow] + bhhf[srow]);
    }
    __syncthreads();

    int wid = tid >> 5, lane = tid & 31;
    int dw = wid / 6, wrem = wid % 6, tauw = wrem >> 1, kh = wrem & 1;

    // register-resident B fragments (constant across all 2000 steps)
    wmma::fragment<wmma::matrix_b, 16, 16, 16, half, wmma::col_major> Bf[10];
#pragma unroll
    for (int i = 0; i < 10; ++i)
        wmma::load_matrix_sync(Bf[i], WhhS + ((dw * 3 + tauw) * 16) * LDW + kh * 160 + i * 16, LDW);

    // state mapping: one thread per (dir, col, batch)
    int sd = tid / 192, srem = tid % 192, scol = srem / 16, sb = srem % 16;
    int stau = scol >> 2, scc = scol & 3;
    float creg = 0.f;
    float bi = bS[sd * 48 + stau * 16 + 0 + scc];
    float bf2 = bS[sd * 48 + stau * 16 + 4 + scc];
    float bg = bS[sd * 48 + stau * 16 + 8 + scc];
    float bo = bS[sd * 48 + stau * 16 + 12 + scc];

    // prefetch z for step 0
    float n0, n1, n2, n3;
    {
        int pos0 = sd ? (Ss - 1) : 0;
        const float* crow = g_C + ((size_t)pos0 * Bb + sb) * NPAD
                            + (sd ? NDIRBASE : 0) + (cta * 3 + stau) * 16;
        n0 = crow[0 + scc]; n1 = crow[4 + scc]; n2 = crow[8 + scc]; n3 = crow[12 + scc];
    }

    for (int g = 0; g < Tt * Ss; ++g) {
        int t = g / Ss, s = g % Ss;
        int parity = g & 1;
        float z0 = n0, z1 = n1, z2 = n2, z3 = n3;

        // per-warp ballot poll: all 25 slots >= g, then acquire fence
        {
            unsigned tgt = (unsigned)g;
            bool mine = (lane < NCTA_L);
            unsigned ok;
            do {
                unsigned f = tgt;
                if (mine)
                    asm volatile("ld.global.relaxed.gpu.u32 %0, [%1];"
                                 : "=r"(f) : "l"(g_slots + lane * 8) : "memory");
                ok = __ballot_sync(0xFFFFFFFFu, (!mine) || (f >= tgt));
            } while (ok != 0xFFFFFFFFu);
            asm volatile("fence.acq_rel.gpu;" ::: "memory");
        }

        // recurrent matmul: A from L2 (g_h), B from registers
        {
            wmma::fragment<wmma::accumulator, 16, 16, 16, float> acc;
            wmma::fill_fragment(acc, 0.f);
            const __half* hbase = g_h + ((size_t)(dw * 2 + parity) * Bb) * LDK + kh * 160;
#pragma unroll
            for (int i = 0; i < 10; ++i) {
                wmma::fragment<wmma::matrix_a, 16, 16, 16, half, wmma::row_major> af;
                wmma::load_matrix_sync(af, hbase + i * 16, LDK);
                wmma::mma_sync(acc, af, Bf[i], acc);
            }
            wmma::store_matrix_sync(accS + wid * 16 * LDA, acc, LDA, wmma::mem_row_major);
        }

        // prefetch next step's z
        if (g + 1 < Tt * Ss) {
            int gn = g + 1;
            int tn = gn / Ss, sn = gn % Ss;
            int posn = sd ? (Ss - 1 - sn) : sn;
            const float* crow = g_C + ((size_t)(tn * Ss + posn) * Bb + sb) * NPAD
                                + (sd ? NDIRBASE : 0) + (cta * 3 + stau) * 16;
            n0 = crow[0 + scc]; n1 = crow[4 + scc]; n2 = crow[8 + scc]; n3 = crow[12 + scc];
        }
        __syncthreads();

        // gates + state update (one state per thread; k-halves summed)
        {
            int pos = sd ? (Ss - 1 - s) : s;
            int w0 = (sd * 3 + stau) * 2;
            const float* a0 = accS + w0 * 16 * LDA + sb * LDA;
            const float* a1 = a0 + 16 * LDA;
            float zi = z0 + bi  + a0[0 + scc]  + a1[0 + scc];
            float zf = z1 + bf2 + a0[4 + scc]  + a1[4 + scc];
            float zg = z2 + bg  + a0[8 + scc]  + a1[8 + scc];
            float zo = z3 + bo  + a0[12 + scc] + a1[12 + scc];
            float ig = sigm(zi);
            float fg = sigm(zf);
            float gg = tanh_fast(zg);
            float og = sigm(zo);
            creg = fg * creg + ig * gg;
            float hval = og * tanh_fast(creg);
            int jh = cta * CPD + scol;
            g_h[((sd * 2 + (parity ^ 1)) * Bb + sb) * LDK + jh] = __float2half(hval);
            g_y[((size_t)(t * Ss + pos) * Bb + sb) * 600 + sd * 300 + jh] = hval;
        }
        __syncthreads();

        // publish: per-CTA release slot (cumulative after the barrier)
        if (tid == 0)
            asm volatile("st.global.release.gpu.u32 [%0], %1;"
                         :: "l"(g_slots + cta * 8), "r"((unsigned)(g + 1)) : "memory");
    }
}

// ---------------- kernel 6: classifier ----------------
__global__ void k_cls(const float* __restrict__ W, const float* __restrict__ bc,
                      float* __restrict__ out) {
    int t = blockIdx.x >> 4, b = blockIdx.x & 15;
    float a0 = 0.f, a1 = 0.f, a2 = 0.f, a3 = 0.f;
    const size_t NW = 120000;
    for (int idx = threadIdx.x; idx < (int)NW; idx += 256) {
        int s = idx / 600, c = idx % 600;
        float yv = g_y[((size_t)(t * Ss + s) * Bb + b) * 600 + c];
        yv = fmaxf(yv, 0.f);
        a0 += yv * W[idx];
        a1 += yv * W[NW + idx];
        a2 += yv * W[2 * NW + idx];
        a3 += yv * W[3 * NW + idx];
    }
#pragma unroll
    for (int off = 16; off; off >>= 1) {
        a0 += __shfl_down_sync(0xFFFFFFFFu, a0, off);
        a1 += __shfl_down_sync(0xFFFFFFFFu, a1, off);
        a2 += __shfl_down_sync(0xFFFFFFFFu, a2, off);
        a3 += __shfl_down_sync(0xFFFFFFFFu, a3, off);
    }
    __shared__ float rs[8][4];
    if ((threadIdx.x & 31) == 0) {
        int w = threadIdx.x >> 5;
        rs[w][0] = a0; rs[w][1] = a1; rs[w][2] = a2; rs[w][3] = a3;
    }
    __syncthreads();
    if (threadIdx.x < 4) {
        float sv = bc[threadIdx.x];
#pragma unroll
        for (int w = 0; w < 8; ++w) sv += rs[w][threadIdx.x];
        out[blockIdx.x * 4 + threadIdx.x] = sv;
    }
}

// ---------------- host launcher ----------------
extern "C" void kernel_launch(void* const* d_in, const int* in_sizes, int n_in,
                              void* d_out, int out_size) {
    const float* seq  = (const float*)d_in[1];
    const float* sp   = (const float*)d_in[2];
    const float* ep   = (const float*)d_in[3];
    const float* cp   = (const float*)d_in[4];
    const float* bsp  = (const float*)d_in[5];
    const float* bep  = (const float*)d_in[6];
    const float* bcp  = (const float*)d_in[7];
    const float* um   = (const float*)d_in[8];
    const float* nm   = (const float*)d_in[9];
    const float* am   = (const float*)d_in[10];
    const float* wihf = (const float*)d_in[11];
    const float* whhf = (const float*)d_in[12];
    const float* bihf = (const float*)d_in[13];
    const float* bhhf = (const float*)d_in[14];
    const float* wihb = (const float*)d_in[15];
    const float* whhb = (const float*)d_in[16];
    const float* bihb = (const float*)d_in[17];
    const float* bhhb = (const float*)d_in[18];
    const float* wcls = (const float*)d_in[19];
    const float* bcls = (const float*)d_in[20];
    float* out = (float*)d_out;

    const int LSTM_SMEM = 2 * 3 * 16 * LDW * 2               // WhhS halves
                        + (12 * 16 * LDA + 96) * 4;          // accS + bS
    cudaFuncSetAttribute(k_lstm, cudaFuncAttributeMaxDynamicSharedMemorySize, LSTM_SMEM);
    cudaFuncSetAttribute(k_gemm2, cudaFuncAttributeMaxDynamicSharedMemorySize, GSMEM);

    k_init<<<40, 256>>>();
    k_weights<<<(Tt * Bb * Ss + 255) / 256, 256>>>(sp, ep, cp, bsp, bep, bcp, um, nm, am);
    k_wpad<<<NPAD, 256>>>(wihf, wihb);
    k_xbuild<<<Mm, 192>>>(seq);
    dim3 gg(NPAD / 128, Mm / 128);
    k_gemm2<<<gg, 256, GSMEM>>>();
    k_lstm<<<NCTA_L, 384, LSTM_SMEM>>>(whhf, whhb, bihf, bhhf, bihb, bhhb);
    k_cls<<<Tt * Bb, 256>>>(wcls, bcls, out);
}

// round 9
// speedup vs baseline: 1.5288x; 1.5288x over previous
#include <cuda_runtime.h>
#include <cuda_fp16.h>
#include <mma.h>
#include <cstdint>
#include <cstddef>

using namespace nvcuda;

#define Tt 10
#define Bb 16
#define Ss 200
#define Dd 768
#define K5 3840            // 5*D
#define NPAD 2432          // 1216 (fwd block) + 1216 (bwd block)
#define NDIRBASE 1216
#define Mm 32000           // T*S*B
#define LDK 320            // padded recurrent K in GLOBAL h buffer (halves)
#define LDW 344            // Whh shared stride (halves)
#define LDA 20             // accS stride (floats)
#define NTILE 75           // gate-tiles per direction
#define NCTA_L 150         // 75 fwd + 75 bwd CTAs

// ---------------- device scratch (allocation-free) ----------------
__device__ __half g_X[(size_t)Mm * K5];      // 245.8 MB fp16
__device__ __half g_W[(size_t)NPAD * K5];    // 18.7 MB fp16
__device__ float g_C[(size_t)Mm * NPAD];     // 311.3 MB
__device__ float g_ws[Tt * Bb * Ss];
__device__ float g_we[Tt * Bb * Ss];
__device__ float g_wbs[Bb * Ss];
__device__ float g_wbe[Bb * Ss];
__device__ float g_y[(size_t)Tt * Ss * Bb * 600];  // [t][s][b][2H]
__device__ __half g_h[2 * 2 * Bb * LDK];     // [dir][parity][b][LDK] fp16
__device__ unsigned g_slots[NCTA_L * 8];     // per-CTA barrier slots, 32B stride

// ---------------- helpers ----------------
__device__ __forceinline__ uint32_t smem_u32(const void* p) {
    uint32_t a;
    asm("{ .reg .u64 t; cvta.to.shared.u64 t, %1; cvt.u32.u64 %0, t; }" : "=r"(a) : "l"(p));
    return a;
}
__device__ __forceinline__ void cp16(uint32_t d, const void* s) {
    asm volatile("cp.async.cg.shared.global [%0], [%1], 16;" :: "r"(d), "l"(s) : "memory");
}

// ---------------- kernel 0: init ----------------
__global__ void k_init() {
    int i = threadIdx.x + blockIdx.x * blockDim.x;
    if (i < NCTA_L * 8) g_slots[i] = 0u;
    for (int e = i; e < 2 * 2 * Bb * LDK; e += gridDim.x * blockDim.x)
        g_h[e] = __float2half(0.f);
}

// ---------------- kernel 1: fused attention weights ----------------
__global__ void k_weights(const float* __restrict__ sp, const float* __restrict__ ep,
                          const float* __restrict__ cp,
                          const float* __restrict__ bsp, const float* __restrict__ bep,
                          const float* __restrict__ bcp,
                          const float* __restrict__ um, const float* __restrict__ nm,
                          const float* __restrict__ am) {
    int idx = blockIdx.x * blockDim.x + threadIdx.x;
    if (idx >= Tt * Bb * Ss) return;
    int t = idx / (Bb * Ss);
    int r = idx % (Bb * Ss);
    int b = r / Ss;
    int s = r % Ss;
    // masks are [B,T,S]
    float amv = am[(b * Tt + t) * Ss + s];
    float umv = um[(b * Tt + t) * Ss + s];
    float nmv = nm[(b * Tt + t) * Ss + s];
    const float* c = cp + (t * Bb + b) * 4;
    float wb = amv * c[0] + umv * c[1] + nmv * c[2];
    g_ws[idx] = sp[idx] * wb;
    g_we[idx] = ep[idx] * wb;
    if (t == 0) {
        const float* bc = bcp + b * 4;
        float wbb = amv * bc[0] + umv * bc[1] + nmv * bc[2];
        g_wbs[b * Ss + s] = bsp[b * Ss + s] * wbb;
        g_wbe[b * Ss + s] = bep[b * Ss + s] * wbb;
    }
}

// ---------------- kernel 2: stacked + gate-permuted fp16 Wih -----------------
__global__ void k_wpad(const float* __restrict__ wf, const float* __restrict__ wb) {
    int rrow = blockIdx.x;
    int dir = rrow >= NDIRBASE;
    int rp = dir ? rrow - NDIRBASE : rrow;
    const float* src = nullptr;
    if (rp < 1200) {
        int tile = rp >> 4, gate = (rp >> 2) & 3, cc = rp & 3;
        int srow = gate * 300 + tile * 4 + cc;
        src = (dir ? wb : wf) + (size_t)srow * K5;
    }
    __half* dst = g_W + (size_t)rrow * K5;
    for (int c = threadIdx.x * 4; c < K5; c += blockDim.x * 4) {
        float4 v = make_float4(0.f, 0.f, 0.f, 0.f);
        if (src) v = *(const float4*)(src + c);
        __half2 a = __floats2half2_rn(v.x, v.y);
        __half2 b2 = __floats2half2_rn(v.z, v.w);
        *(__half2*)(dst + c) = a;
        *(__half2*)(dst + c + 2) = b2;
    }
}

// ---------------- kernel 3: build X (fp16) ----------------
__global__ void k_xbuild(const float* __restrict__ seq) {
    int m = blockIdx.x;          // ((t*200+s)*16+b)
    int b = m & 15;
    int ts = m >> 4;
    int s = ts % Ss;
    int t = ts / Ss;
    int tp = (t > 0) ? (t - 1) : 0;
    int c = threadIdx.x * 4;     // 192 threads -> 768 cols
    const float4 sv = *(const float4*)(seq + (((size_t)(t * Bb + b) * Ss + s) * Dd) + c);
    const float4 pv = *(const float4*)(seq + (((size_t)(tp * Bb + b) * Ss + s) * Dd) + c);
    int widx = (t * Bb + b) * Ss + s;
    float w1 = g_ws[widx], w2 = g_we[widx];
    float wp1, wp2;
    if (t > 0) {
        int pidx = ((t - 1) * Bb + b) * Ss + s;
        wp1 = g_ws[pidx];
        wp2 = g_we[pidx];
    } else {
        wp1 = g_wbs[b * Ss + s];
        wp2 = g_wbe[b * Ss + s];
    }
    __half* X = g_X + (size_t)m * K5 + c;
#define R4(off, a, wgt) do { \
        __half2 _h0 = __floats2half2_rn((a).x * (wgt), (a).y * (wgt)); \
        __half2 _h1 = __floats2half2_rn((a).z * (wgt), (a).w * (wgt)); \
        *(__half2*)(X + (off)) = _h0; \
        *(__half2*)(X + (off) + 2) = _h1; } while (0)
    R4(0,    sv, 1.f);
    R4(768,  sv, w1);
    R4(1536, sv, w2);
    R4(2304, pv, wp1);
    R4(3072, pv, wp2);
#undef R4
}

// ---------------- kernel 4: pipelined fp16 wmma GEMM  C = X * W^T ------------
#define GP2 40
#define STAGEH (2 * 128 * GP2)         // halves per stage (A + B)
#define GSMEM (3 * STAGEH * 2)         // 61440 B -> 2 CTAs/SM
#define NK (K5 / 32)                   // 120 k-tiles

__global__ void __launch_bounds__(256) k_gemm2() {
    extern __shared__ __half smh[];
    int tid = threadIdx.x;
    int mt = blockIdx.y, nt = blockIdx.x;
    uint32_t sbase = smem_u32(smh);

    int wid = tid >> 5;
    int wy = wid >> 1, wx = wid & 1;   // 4x2 warps; warp tile 32x64

    int lrow0 = tid >> 2;              // 64 rows per pass, 2 passes
    int lc4 = tid & 3;                 // 4 chunks of 8 halves per row

    const __half* AG = g_X + (size_t)(mt * 128) * K5;
    const __half* BG = g_W + (size_t)(nt * 128) * K5;

    wmma::fragment<wmma::accumulator, 16, 16, 16, float> acc[2][4];
#pragma unroll
    for (int i = 0; i < 2; ++i)
#pragma unroll
        for (int j = 0; j < 4; ++j) wmma::fill_fragment(acc[i][j], 0.f);

#define LOADSTAGE(kt, st) do { \
        uint32_t sa = sbase + (st) * STAGEH * 2; \
        uint32_t sbb = sa + 128 * GP2 * 2; \
        int kof = (kt) * 32 + lc4 * 8; \
        _Pragma("unroll") \
        for (int i = 0; i < 2; ++i) { \
            int row = lrow0 + i * 64; \
            cp16(sa  + (row * GP2 + lc4 * 8) * 2, AG + (size_t)row * K5 + kof); \
            cp16(sbb + (row * GP2 + lc4 * 8) * 2, BG + (size_t)row * K5 + kof); \
        } \
        asm volatile("cp.async.commit_group;" ::: "memory"); \
    } while (0)

    LOADSTAGE(0, 0);
    LOADSTAGE(1, 1);

    for (int kt = 0; kt < NK; ++kt) {
        int st = kt % 3;
        asm volatile("cp.async.wait_group 1;" ::: "memory");
        __syncthreads();
        if (kt + 2 < NK) {
            LOADSTAGE(kt + 2, (kt + 2) % 3);
        } else {
            asm volatile("cp.async.commit_group;" ::: "memory");
        }
        const __half* As = smh + st * STAGEH;
        const __half* Bs = As + 128 * GP2;
#pragma unroll
        for (int ks = 0; ks < 2; ++ks) {
            wmma::fragment<wmma::matrix_a, 16, 16, 16, half, wmma::row_major> a0, a1;
            wmma::load_matrix_sync(a0, As + (wy * 32) * GP2 + ks * 16, GP2);
            wmma::load_matrix_sync(a1, As + (wy * 32 + 16) * GP2 + ks * 16, GP2);
#pragma unroll
            for (int j = 0; j < 4; ++j) {
                wmma::fragment<wmma::matrix_b, 16, 16, 16, half, wmma::col_major> bf;
                wmma::load_matrix_sync(bf, Bs + (wx * 64 + j * 16) * GP2 + ks * 16, GP2);
                wmma::mma_sync(acc[0][j], a0, bf, acc[0][j]);
                wmma::mma_sync(acc[1][j], a1, bf, acc[1][j]);
            }
        }
    }
#undef LOADSTAGE

#pragma unroll
    for (int i = 0; i < 2; ++i)
#pragma unroll
        for (int j = 0; j < 4; ++j) {
            float* cp = g_C + (size_t)(mt * 128 + wy * 32 + i * 16) * NPAD
                        + nt * 128 + wx * 64 + j * 16;
            wmma::store_matrix_sync(cp, acc[i][j], NPAD, wmma::mem_row_major);
        }
}

// ---------------- kernel 5: direction-split persistent LSTM scan -------------
// 150 CTAs x 128 threads: CTA < 75 -> forward tile, CTA >= 75 -> backward tile.
// Each CTA: one 16-gate-row tile of ONE direction; 4 warps k-split x4;
// Whh B-frags register-resident; A-frags from L2; independent per-dir barriers.
__device__ __forceinline__ float sigm(float x) {
    return 1.f / (1.f + __expf(-x));
}
__device__ __forceinline__ float tanh_fast(float x) {
    x = fminf(fmaxf(x, -15.f), 15.f);
    float e = __expf(-2.f * x);
    return (1.f - e) / (1.f + e);
}

__global__ void __launch_bounds__(128, 2) k_lstm(
        const float* __restrict__ whf, const float* __restrict__ whb,
        const float* __restrict__ bihf, const float* __restrict__ bhhf,
        const float* __restrict__ bihb, const float* __restrict__ bhhb) {
    __shared__ __half WhhS[16 * LDW];        // prologue staging only
    __shared__ float accS[4 * 16 * LDA];
    __shared__ float bS[16];

    int tid = threadIdx.x;
    int cta = blockIdx.x;
    int dir = (cta >= NTILE) ? 1 : 0;
    int tile = dir ? (cta - NTILE) : cta;
    const float* wh = dir ? whb : whf;

    // prologue: gate-permuted Whh tile into shared (fp16)
    for (int e = tid; e < 16 * LDW; e += 128) {
        int k = e % LDW;
        int rr = e / LDW;
        int gate = rr >> 2, cc = rr & 3;
        int srow = gate * 300 + tile * 4 + cc;
        float v = 0.f;
        if (k < 300) v = wh[srow * 300 + k];
        WhhS[e] = __float2half(v);
    }
    if (tid < 16) {
        int gate = tid >> 2, cc = tid & 3;
        int srow = gate * 300 + tile * 4 + cc;
        bS[tid] = dir ? (bihb[srow] + bhhb[srow]) : (bihf[srow] + bhhf[srow]);
    }
    __syncthreads();

    int kq = tid >> 5;                       // warp = k-quarter (0..3)

    // register-resident B fragments (constant across all 2000 steps)
    wmma::fragment<wmma::matrix_b, 16, 16, 16, half, wmma::col_major> Bf[5];
#pragma unroll
    for (int i = 0; i < 5; ++i)
        wmma::load_matrix_sync(Bf[i], WhhS + kq * 80 + i * 16, LDW);

    // state mapping: tid<64 -> (col scc, batch sb)
    int scc = tid >> 4, sb = tid & 15;       // valid for tid<64
    float creg = 0.f;
    float bi = 0.f, bf2 = 0.f, bg = 0.f, bo = 0.f;
    if (tid < 64) {
        bi  = bS[0 + scc];
        bf2 = bS[4 + scc];
        bg  = bS[8 + scc];
        bo  = bS[12 + scc];
    }

    // z prefetch for step 0
    float n0 = 0.f, n1 = 0.f, n2 = 0.f, n3 = 0.f;
    if (tid < 64) {
        int pos0 = dir ? (Ss - 1) : 0;
        const float* crow = g_C + ((size_t)pos0 * Bb + sb) * NPAD
                            + (dir ? NDIRBASE : 0) + tile * 16;
        n0 = crow[0 + scc]; n1 = crow[4 + scc]; n2 = crow[8 + scc]; n3 = crow[12 + scc];
    }

    const unsigned* myslots = g_slots + dir * NTILE * 8;

    for (int g = 0; g < Tt * Ss; ++g) {
        int t = g / Ss, s = g % Ss;
        int parity = g & 1;
        float z0 = n0, z1 = n1, z2 = n2, z3 = n3;

        // wait: all 75 CTAs of THIS direction published step g-1
        if (g > 0) {
            if (tid < NTILE) {
                unsigned f;
                do {
                    asm volatile("ld.global.relaxed.gpu.u32 %0, [%1];"
                                 : "=r"(f) : "l"(myslots + tid * 8) : "memory");
                } while (f < (unsigned)g);
            }
            __syncthreads();
            asm volatile("fence.acq_rel.gpu;" ::: "memory");
        }

        // recurrent matmul: A from L2 (g_h), B from registers
        {
            wmma::fragment<wmma::accumulator, 16, 16, 16, float> acc;
            wmma::fill_fragment(acc, 0.f);
            const __half* hbase = g_h + ((size_t)(dir * 2 + parity) * Bb) * LDK + kq * 80;
#pragma unroll
            for (int i = 0; i < 5; ++i) {
                wmma::fragment<wmma::matrix_a, 16, 16, 16, half, wmma::row_major> af;
                wmma::load_matrix_sync(af, hbase + i * 16, LDK);
                wmma::mma_sync(acc, af, Bf[i], acc);
            }
            wmma::store_matrix_sync(accS + kq * 16 * LDA, acc, LDA, wmma::mem_row_major);
        }

        // prefetch next step's z
        if (tid < 64 && g + 1 < Tt * Ss) {
            int gn = g + 1;
            int tn = gn / Ss, sn = gn % Ss;
            int posn = dir ? (Ss - 1 - sn) : sn;
            const float* crow = g_C + ((size_t)(tn * Ss + posn) * Bb + sb) * NPAD
                                + (dir ? NDIRBASE : 0) + tile * 16;
            n0 = crow[0 + scc]; n1 = crow[4 + scc]; n2 = crow[8 + scc]; n3 = crow[12 + scc];
        }
        __syncthreads();

        // gates + state update (64 states: 4 cols x 16 batches)
        if (tid < 64) {
            int pos = dir ? (Ss - 1 - s) : s;
            const float* a0 = accS + sb * LDA;
            const int W1 = 16 * LDA, W2 = 32 * LDA, W3 = 48 * LDA;
            float zi = z0 + bi  + a0[0 + scc]  + a0[W1 + 0 + scc]  + a0[W2 + 0 + scc]  + a0[W3 + 0 + scc];
            float zf = z1 + bf2 + a0[4 + scc]  + a0[W1 + 4 + scc]  + a0[W2 + 4 + scc]  + a0[W3 + 4 + scc];
            float zg = z2 + bg  + a0[8 + scc]  + a0[W1 + 8 + scc]  + a0[W2 + 8 + scc]  + a0[W3 + 8 + scc];
            float zo = z3 + bo  + a0[12 + scc] + a0[W1 + 12 + scc] + a0[W2 + 12 + scc] + a0[W3 + 12 + scc];
            float ig = sigm(zi);
            float fg = sigm(zf);
            float gg = tanh_fast(zg);
            float og = sigm(zo);
            creg = fg * creg + ig * gg;
            float hval = og * tanh_fast(creg);
            int jh = tile * 4 + scc;
            g_h[((dir * 2 + (parity ^ 1)) * Bb + sb) * LDK + jh] = __float2half(hval);
            g_y[((size_t)(t * Ss + pos) * Bb + sb) * 600 + dir * 300 + jh] = hval;
        }
        __syncthreads();

        // publish (release after barrier: cumulative for the whole CTA)
        if (tid == 0)
            asm volatile("st.global.release.gpu.u32 [%0], %1;"
                         :: "l"(g_slots + cta * 8), "r"((unsigned)(g + 1)) : "memory");
    }
}

// ---------------- kernel 6: classifier ----------------
__global__ void k_cls(const float* __restrict__ W, const float* __restrict__ bc,
                      float* __restrict__ out) {
    int t = blockIdx.x >> 4, b = blockIdx.x & 15;
    float a0 = 0.f, a1 = 0.f, a2 = 0.f, a3 = 0.f;
    const size_t NW = 120000;
    for (int idx = threadIdx.x; idx < (int)NW; idx += 256) {
        int s = idx / 600, c = idx % 600;
        float yv = g_y[((size_t)(t * Ss + s) * Bb + b) * 600 + c];
        yv = fmaxf(yv, 0.f);
        a0 += yv * W[idx];
        a1 += yv * W[NW + idx];
        a2 += yv * W[2 * NW + idx];
        a3 += yv * W[3 * NW + idx];
    }
#pragma unroll
    for (int off = 16; off; off >>= 1) {
        a0 += __shfl_down_sync(0xFFFFFFFFu, a0, off);
        a1 += __shfl_down_sync(0xFFFFFFFFu, a1, off);
        a2 += __shfl_down_sync(0xFFFFFFFFu, a2, off);
        a3 += __shfl_down_sync(0xFFFFFFFFu, a3, off);
    }
    __shared__ float rs[8][4];
    if ((threadIdx.x & 31) == 0) {
        int w = threadIdx.x >> 5;
        rs[w][0] = a0; rs[w][1] = a1; rs[w][2] = a2; rs[w][3] = a3;
    }
    __syncthreads();
    if (threadIdx.x < 4) {
        float sv = bc[threadIdx.x];
#pragma unroll
        for (int w = 0; w < 8; ++w) sv += rs[w][threadIdx.x];
        out[blockIdx.x * 4 + threadIdx.x] = sv;
    }
}

// ---------------- host launcher ----------------
extern "C" void kernel_launch(void* const* d_in, const int* in_sizes, int n_in,
                              void* d_out, int out_size) {
    const float* seq  = (const float*)d_in[1];
    const float* sp   = (const float*)d_in[2];
    const float* ep   = (const float*)d_in[3];
    const float* cp   = (const float*)d_in[4];
    const float* bsp  = (const float*)d_in[5];
    const float* bep  = (const float*)d_in[6];
    const float* bcp  = (const float*)d_in[7];
    const float* um   = (const float*)d_in[8];
    const float* nm   = (const float*)d_in[9];
    const float* am   = (const float*)d_in[10];
    const float* wihf = (const float*)d_in[11];
    const float* whhf = (const float*)d_in[12];
    const float* bihf = (const float*)d_in[13];
    const float* bhhf = (const float*)d_in[14];
    const float* wihb = (const float*)d_in[15];
    const float* whhb = (const float*)d_in[16];
    const float* bihb = (const float*)d_in[17];
    const float* bhhb = (const float*)d_in[18];
    const float* wcls = (const float*)d_in[19];
    const float* bcls = (const float*)d_in[20];
    float* out = (float*)d_out;

    cudaFuncSetAttribute(k_gemm2, cudaFuncAttributeMaxDynamicSharedMemorySize, GSMEM);

    k_init<<<40, 256>>>();
    k_weights<<<(Tt * Bb * Ss + 255) / 256, 256>>>(sp, ep, cp, bsp, bep, bcp, um, nm, am);
    k_wpad<<<NPAD, 256>>>(wihf, wihb);
    k_xbuild<<<Mm, 192>>>(seq);
    dim3 gg(NPAD / 128, Mm / 128);
    k_gemm2<<<gg, 256, GSMEM>>>();
    k_lstm<<<NCTA_L, 128>>>(whhf, whhb, bihf, bhhf, bihb, bhhb);
    k_cls<<<Tt * Bb, 256>>>(wcls, bcls, out);
}